// round 14
// baseline (speedup 1.0000x reference)
#include <cuda_runtime.h>
#include <cuda_fp16.h>
#include <math.h>
#include <stdint.h>

// Problem constants
#define Bq   8
#define Nn   8192
#define Hh   256
#define Ff   320
#define Ss   32
#define Mtot (Bq * Nn)      // 65536
#define NSPLIT 64
#define NGRP 37             // CTA groups per ys-slice (148 = 37*4)
#define NTILE 512           // M-tiles (65536/128)

// Scratch (static device globals — no cudaMalloc allowed)
__device__ float g_xall[(size_t)Mtot * Hh];        // gated features [B*N, H]
__device__ float g_np[4 * Mtot];                   // partial norm^2 (ys 0..3)
__device__ float g_part[(size_t)NSPLIT * Bq * Ss * Hh];  // split-K partials
// combined weights [Wi;Wj] = 512 rows x 320 cols, fp16,
// tiled as [kchunk 10][n 512][k 32]
__device__ __half g_w[512 * Ff];

// ======================= helpers ============================================
__device__ __forceinline__ uint32_t smem_u32(const void* p) {
    uint32_t a;
    asm("{ .reg .u64 t; cvta.to.shared.u64 t, %1; cvt.u32.u64 %0, t; }"
        : "=r"(a) : "l"(p));
    return a;
}
// SW64 swizzle for 64B rows: bits[5:4] ^= bits[8:7]
__device__ __forceinline__ uint32_t swz(uint32_t o) {
    return o ^ ((o >> 3) & 0x30);
}
__device__ __forceinline__ void cp16(uint32_t dst, const void* src) {
    asm volatile("cp.async.cg.shared.global [%0], [%1], 16;"
                 :: "r"(dst), "l"(src) : "memory");
}
#define CP_COMMIT() asm volatile("cp.async.commit_group;" ::: "memory")
#define CP_WAIT0()  asm volatile("cp.async.wait_group 0;" ::: "memory")

#define LDSM4(r, addr)                                                         \
    asm volatile("ldmatrix.sync.aligned.m8n8.x4.shared.b16 {%0,%1,%2,%3}, [%4];" \
                 : "=r"((r)[0]), "=r"((r)[1]), "=r"((r)[2]), "=r"((r)[3])      \
                 : "r"(addr))

__device__ __forceinline__ void mma16816h(float* d, const uint32_t* a,
                                          uint32_t b0, uint32_t b1) {
    asm volatile(
        "mma.sync.aligned.m16n8k16.row.col.f32.f16.f16.f32 "
        "{%0,%1,%2,%3}, {%4,%5,%6,%7}, {%8,%9}, {%0,%1,%2,%3};"
        : "+f"(d[0]), "+f"(d[1]), "+f"(d[2]), "+f"(d[3])
        : "r"(a[0]), "r"(a[1]), "r"(a[2]), "r"(a[3]), "r"(b0), "r"(b1));
}

// packed f32x2 helpers (k_pool)
__device__ __forceinline__ unsigned long long pk2(float lo, float hi) {
    unsigned long long r;
    asm("mov.b64 %0, {%1, %2};" : "=l"(r) : "f"(lo), "f"(hi));
    return r;
}
__device__ __forceinline__ unsigned long long fma2(unsigned long long a,
                                                   unsigned long long b,
                                                   unsigned long long c) {
    unsigned long long d;
    asm("fma.rn.f32x2 %0, %1, %2, %3;" : "=l"(d) : "l"(a), "l"(b), "l"(c));
    return d;
}
__device__ __forceinline__ float2 upk2(unsigned long long v) {
    float lo, hi;
    asm("mov.b64 {%0, %1}, %2;" : "=f"(lo), "=f"(hi) : "l"(v));
    return make_float2(lo, hi);
}

__device__ __forceinline__ float gate_fn(float zi, float zj) {
    float s = 1.0f / (1.0f + expf(-zi));
    return s * tanhf(zj);
}

// SMEM map (dynamic):
//  [0, 81920)      B resident: 10 chunks x (128 rows x 64B), SW64 per chunk
//  [81920, 98304)  A double buffer: 2 x 8KB (128 rows x 64B)
//  [98304, 99328)  norm buffer 256 f32
#define SM_A   81920
#define SM_NB  98304
#define SM_TOT 99328

// ============================================================================
// k_wconv: convert+tile weights: g_w[(c*512+n)*32+kk], f = c*32+kk
// ============================================================================
__global__ __launch_bounds__(256) void k_wconv(const float* __restrict__ Wi,
                                               const float* __restrict__ Wj) {
    int i = blockIdx.x * 256 + threadIdx.x;   // 0..163839
    int c  = i >> 14;
    int r  = i & 16383;
    int n  = r >> 5;
    int kk = r & 31;
    int f  = c * 32 + kk;
    float v = (n < 256) ? Wi[n * Ff + f] : Wj[(n - 256) * Ff + f];
    g_w[i] = __float2half_rn(v);
}

// ============================================================================
// k_gemm_mma: persistent dual GEMM (fp16 HMMA) + in-register gate + norm.
// 148 CTAs x 512 thr. CTA: ys = bid&3 (h-slice 64), group g = bid>>2.
// M-tiles: m = g + 37*k. B (10 chunks x 128 rows, Di/Dj interleaved per
// 16-row block) resident in smem for the whole kernel.
// Warp (wm=wid>>1, wn=wid&1): 16m x 64n; bn-frag q=wn*4+bn holds
// Di h0+q*8..+8 (rows q*16..+8) and Dj same h (rows q*16+8..+16).
// ============================================================================
__global__ __launch_bounds__(512, 1) void k_gemm_mma(
    const float* __restrict__ x,
    const float* __restrict__ bi, const float* __restrict__ bj)
{
    extern __shared__ __align__(128) char smem[];
    const uint32_t sb = smem_u32(smem);
    const int t    = threadIdx.x;
    const int lane = t & 31;
    const int wid  = t >> 5;
    const int wm   = wid >> 1;            // 0..7
    const int wn   = wid & 1;             // 0..1
    const int ys   = blockIdx.x & 3;      // h-slice
    const int g    = blockIdx.x >> 2;     // 0..36
    const int ntiles = (g < 31) ? 14 : 13;

    // ---- bias in registers: h = ys*64 + (wn*4+bn)*8 + (lane&3)*2 + c
    float bir[8], bjr[8];
#pragma unroll
    for (int bn = 0; bn < 4; bn++) {
#pragma unroll
        for (int c = 0; c < 2; c++) {
            int h = ys * 64 + (wn * 4 + bn) * 8 + (lane & 3) * 2 + c;
            bir[bn * 2 + c] = bi[h];
            bjr[bn * 2 + c] = bj[h];
        }
    }

    // ---- prologue: load resident B (80KB, 10 chunks) via cp.async
    // chunk c, local row rloc = q*16 + d*8 + rr -> global n = d*256 + ys*64 + q*8 + rr
#pragma unroll
    for (int i = 0; i < 10; i++) {
        int e    = t + i * 512;            // 0..5119
        int c    = e >> 9;
        int er   = e & 511;
        int rloc = er >> 2;
        int kc   = er & 3;
        int q  = rloc >> 4;
        int d  = (rloc >> 3) & 1;
        int rr = rloc & 7;
        int n  = d * 256 + ys * 64 + q * 8 + rr;
        cp16(sb + c * 8192 + swz((uint32_t)rloc * 64 + kc * 16),
             g_w + (size_t)c * 16384 + (size_t)n * 32 + kc * 8);
    }
    CP_COMMIT();

    // A addressing: thread owns row t>>2, 8 floats at col (t&3)*8
    const int xrow = t >> 2, xc = t & 3;

    // ---- A convert fp32 -> fp16, STS swizzled into buffer st
    auto stsA = [&](float4 v0, float4 v1, int st) {
        __half2 h0 = __floats2half2_rn(v0.x, v0.y);
        __half2 h1 = __floats2half2_rn(v0.z, v0.w);
        __half2 h2 = __floats2half2_rn(v1.x, v1.y);
        __half2 h3 = __floats2half2_rn(v1.z, v1.w);
        uint4 pv = make_uint4(*(uint32_t*)&h0, *(uint32_t*)&h1,
                              *(uint32_t*)&h2, *(uint32_t*)&h3);
        *(uint4*)(smem + SM_A + st * 8192 + swz((uint32_t)xrow * 64 + xc * 16)) = pv;
    };

    const uint32_t arowoff = (uint32_t)(wm * 16 + (lane & 7) + ((lane >> 3) & 1) * 8) * 64
                             + ((lane >> 4) & 1) * 16;
    const uint32_t browoff = (uint32_t)(wn * 64 + (lane & 7) + ((lane >> 3) & 1) * 8) * 64
                             + ((lane >> 4) & 1) * 16;

    float acc[8][4];
    float* nbuf = (float*)(smem + SM_NB);

    // first tile chunk 0 A
    {
        int m0 = g * 128;
        const float* xp = x + (size_t)(m0 + xrow) * Ff + xc * 8;
        float4 v0 = *(const float4*)xp;
        float4 v1 = *(const float4*)(xp + 4);
        CP_WAIT0();                        // B resident
        stsA(v0, v1, 0);
    }

    for (int kt = 0; kt < ntiles; kt++) {
        const int m0 = (g + 37 * kt) * 128;
        const float* xptr = x + (size_t)(m0 + xrow) * Ff + xc * 8;
#pragma unroll
        for (int i = 0; i < 8; i++) { acc[i][0]=0.f; acc[i][1]=0.f; acc[i][2]=0.f; acc[i][3]=0.f; }

        for (int it = 0; it < 10; it++) {
            const int buf = it & 1;
            __syncthreads();               // A(it) visible; prev compute done
            // prefetch next chunk (this tile or next tile's chunk 0)
            float4 xn0, xn1;
            bool pf = false;
            if (it < 9) {
                xn0 = *(const float4*)(xptr + (it + 1) * 32);
                xn1 = *(const float4*)(xptr + (it + 1) * 32 + 4);
                pf = true;
            } else if (kt + 1 < ntiles) {
                const float* xq = x + (size_t)((g + 37 * (kt + 1)) * 128 + xrow) * Ff + xc * 8;
                xn0 = *(const float4*)xq;
                xn1 = *(const float4*)(xq + 4);
                pf = true;
            }
            // compute chunk it: A from buf, B resident chunk it
            {
                uint32_t aB = sb + SM_A + buf * 8192;
                uint32_t bB = sb + it * 8192;
#pragma unroll
                for (int k16 = 0; k16 < 2; k16++) {
                    uint32_t a4[4];
                    LDSM4(a4, aB + swz(arowoff + k16 * 32));
#pragma unroll
                    for (int bn = 0; bn < 4; bn++) {
                        uint32_t b4[4];
                        LDSM4(b4, bB + swz(browoff + (uint32_t)bn * 16 * 64 + k16 * 32));
                        mma16816h(acc[bn * 2],     a4, b4[0], b4[2]);
                        mma16816h(acc[bn * 2 + 1], a4, b4[1], b4[3]);
                    }
                }
            }
            if (pf) stsA(xn0, xn1, buf ^ 1);
        }

        // ---- epilogue: in-register gate + STG + norm partials
        const int r0 = m0 + wm * 16 + (lane >> 2);
        const int hg = ys * 64 + wn * 32 + (lane & 3) * 2;
        float nrm0 = 0.0f, nrm1 = 0.0f;
#pragma unroll
        for (int bn = 0; bn < 4; bn++) {
            float o00 = gate_fn(acc[bn*2][0] + bir[bn*2],   acc[bn*2+1][0] + bjr[bn*2]);
            float o01 = gate_fn(acc[bn*2][1] + bir[bn*2+1], acc[bn*2+1][1] + bjr[bn*2+1]);
            float o10 = gate_fn(acc[bn*2][2] + bir[bn*2],   acc[bn*2+1][2] + bjr[bn*2]);
            float o11 = gate_fn(acc[bn*2][3] + bir[bn*2+1], acc[bn*2+1][3] + bjr[bn*2+1]);
            int h = hg + bn * 8;
            *(float2*)&g_xall[(size_t)r0 * Hh + h]       = make_float2(o00, o01);
            *(float2*)&g_xall[(size_t)(r0 + 8) * Hh + h] = make_float2(o10, o11);
            nrm0 += o00 * o00 + o01 * o01;
            nrm1 += o10 * o10 + o11 * o11;
        }
        nrm0 += __shfl_xor_sync(0xFFFFFFFFu, nrm0, 1);
        nrm0 += __shfl_xor_sync(0xFFFFFFFFu, nrm0, 2);
        nrm1 += __shfl_xor_sync(0xFFFFFFFFu, nrm1, 1);
        nrm1 += __shfl_xor_sync(0xFFFFFFFFu, nrm1, 2);
        if ((lane & 3) == 0) {
            nbuf[wn * 128 + wm * 16 + (lane >> 2)]     = nrm0;
            nbuf[wn * 128 + wm * 16 + (lane >> 2) + 8] = nrm1;
        }
        __syncthreads();
        if (t < 128)
            g_np[(size_t)ys * Mtot + m0 + t] = nbuf[t] + nbuf[128 + t];
        // nbuf reads are in regs before the next tile's first __syncthreads;
        // next writes happen only after that barrier -> safe.
    }
}

// ============================================================================
// k_weight: masked softmax over nodes. One block per (b,s).
// norm = sqrt(p0+p1+p2+p3) from the four GEMM ys-partials.
// ============================================================================
__global__ __launch_bounds__(256) void k_weight(const float* __restrict__ node_map,
                                                float* __restrict__ wout) {
    __shared__ float e[Nn];
    __shared__ float red[256];
    int bs = blockIdx.x;
    int b  = bs >> 5;
    const float* nm  = node_map + (size_t)bs * Nn;
    const float* np0 = g_np + (size_t)b * Nn;
    const float* np1 = g_np + (size_t)Mtot + (size_t)b * Nn;
    const float* np2 = g_np + (size_t)2 * Mtot + (size_t)b * Nn;
    const float* np3 = g_np + (size_t)3 * Mtot + (size_t)b * Nn;
    int t = threadIdx.x;
    float part = 0.0f;
    for (int n = t; n < Nn; n += 256) {
        float v  = nm[n] * sqrtf(np0[n] + np1[n] + np2[n] + np3[n]);
        float ev = (v > 0.0f) ? expf(v) : 0.0f;
        e[n] = ev;
        part += ev;
    }
    red[t] = part;
    __syncthreads();
#pragma unroll
    for (int o = 128; o > 0; o >>= 1) {
        if (t < o) red[t] += red[t + o];
        __syncthreads();
    }
    float sum = red[0];
    float inv = (sum > 0.0f) ? (1.0f / sum) : 0.0f;
    float* wrow = wout + (size_t)bs * Nn;
    for (int n = t; n < Nn; n += 256) wrow[n] = e[n] * inv;
}

// ============================================================================
// k_pool: split-K pooled partials, full-H blocks, FFMA2.
// ============================================================================
__global__ __launch_bounds__(256) void k_pool(const float* __restrict__ w) {
    __shared__ float xs[32][256];   // 32 KB
    __shared__ float ws[32][32];    //  4 KB
    const int chunk = blockIdx.x;
    const int b     = blockIdx.z;
    const int t     = threadIdx.x;
    const int h1 = (t & 31) * 4;
    const int sq = (t >> 5) * 4;
    const int nbase = chunk * (Nn / NSPLIT);

    unsigned long long acc2[4][4];
    const unsigned long long zz = pk2(0.0f, 0.0f);
#pragma unroll
    for (int i = 0; i < 4; i++)
#pragma unroll
        for (int j = 0; j < 4; j++) acc2[i][j] = zz;

    for (int n0 = 0; n0 < Nn / NSPLIT; n0 += 32) {
        __syncthreads();
#pragma unroll
        for (int i = 0; i < 8; i++) {
            int e  = t + i * 256;
            int nn = e >> 6;
            int hh = (e & 63) * 4;
            *(float4*)&xs[nn][hh] =
                *(const float4*)&g_xall[(size_t)(b * Nn + nbase + n0 + nn) * Hh + hh];
        }
        {
            int s  = t >> 3;
            int nn = (t & 7) * 4;
            float4 wv = *(const float4*)&w[(size_t)(b * Ss + s) * Nn + nbase + n0 + nn];
            ws[nn + 0][s] = wv.x; ws[nn + 1][s] = wv.y;
            ws[nn + 2][s] = wv.z; ws[nn + 3][s] = wv.w;
        }
        __syncthreads();
#pragma unroll
        for (int nc = 0; nc < 32; nc++) {
            ulonglong2 xa = *(const ulonglong2*)&xs[nc][h1];
            ulonglong2 xb = *(const ulonglong2*)&xs[nc][128 + h1];
            float4 wv = *(const float4*)&ws[nc][sq];
            unsigned long long wp[4];
            wp[0] = pk2(wv.x, wv.x); wp[1] = pk2(wv.y, wv.y);
            wp[2] = pk2(wv.z, wv.z); wp[3] = pk2(wv.w, wv.w);
#pragma unroll
            for (int i = 0; i < 4; i++) {
                acc2[i][0] = fma2(wp[i], xa.x, acc2[i][0]);
                acc2[i][1] = fma2(wp[i], xa.y, acc2[i][1]);
                acc2[i][2] = fma2(wp[i], xb.x, acc2[i][2]);
                acc2[i][3] = fma2(wp[i], xb.y, acc2[i][3]);
            }
        }
    }
#pragma unroll
    for (int i = 0; i < 4; i++) {
        float2 a0 = upk2(acc2[i][0]), a1 = upk2(acc2[i][1]);
        float2 b0 = upk2(acc2[i][2]), b1 = upk2(acc2[i][3]);
        size_t base = (size_t)((chunk * Bq + b) * Ss + sq + i) * Hh;
        *(float4*)&g_part[base + h1]       = make_float4(a0.x, a0.y, a1.x, a1.y);
        *(float4*)&g_part[base + 128 + h1] = make_float4(b0.x, b0.y, b1.x, b1.y);
    }
}

// ============================================================================
// k_final: deterministic split-K reduce + tanh
// ============================================================================
__global__ __launch_bounds__(256) void k_final(float* __restrict__ out) {
    int g = blockIdx.x * blockDim.x + threadIdx.x;
    float s = 0.0f;
#pragma unroll
    for (int c = 0; c < NSPLIT; c++) s += g_part[(size_t)c * (Bq * Ss * Hh) + g];
    out[g] = tanhf(s);
}

// ============================================================================
extern "C" void kernel_launch(void* const* d_in, const int* in_sizes, int n_in,
                              void* d_out, int out_size) {
    const float* x        = (const float*)d_in[0];
    const float* node_map = (const float*)d_in[1];
    const float* Wi       = (const float*)d_in[2];
    const float* bi       = (const float*)d_in[3];
    const float* Wj       = (const float*)d_in[4];
    const float* bj       = (const float*)d_in[5];
    float* out  = (float*)d_out;
    float* wout = out + (size_t)Bq * Ss * Hh;

    cudaFuncSetAttribute(k_gemm_mma, cudaFuncAttributeMaxDynamicSharedMemorySize, SM_TOT);

    k_wconv<<<(512 * Ff) / 256, 256>>>(Wi, Wj);
    k_gemm_mma<<<148, 512, SM_TOT>>>(x, bi, bj);
    k_weight<<<Bq * Ss, 256>>>(node_map, wout);
    k_pool<<<dim3(NSPLIT, 1, Bq), 256>>>(wout);
    k_final<<<(Bq * Ss * Hh) / 256, 256>>>(out);
}

// round 15
// speedup vs baseline: 1.0685x; 1.0685x over previous
#include <cuda_runtime.h>
#include <cuda_fp16.h>
#include <math.h>
#include <stdint.h>

// Problem constants
#define Bq   8
#define Nn   8192
#define Hh   256
#define Ff   320
#define Ss   32
#define Mtot (Bq * Nn)      // 65536
#define NSPLIT 64

// Scratch (static device globals — no cudaMalloc allowed)
__device__ __half g_xh[(size_t)Mtot * Hh];         // gated features fp16 [B*N, H]
__device__ float g_np[2 * Mtot];                   // partial norm^2 (nt 0/1)
__device__ float g_part[(size_t)NSPLIT * Bq * Ss * Hh];  // split-K partials
// combined weights [Wi;Wj] = 512 rows x 320 cols, fp16,
// tiled as [kchunk 10][n 512][k 32] for direct cp.async
__device__ __half g_w[512 * Ff];

// ======================= helpers ============================================
__device__ __forceinline__ uint32_t smem_u32(const void* p) {
    uint32_t a;
    asm("{ .reg .u64 t; cvta.to.shared.u64 t, %1; cvt.u32.u64 %0, t; }"
        : "=r"(a) : "l"(p));
    return a;
}
// SW64 swizzle for 64B rows: bits[5:4] ^= bits[8:7]
__device__ __forceinline__ uint32_t swz(uint32_t o) {
    return o ^ ((o >> 3) & 0x30);
}
__device__ __forceinline__ void cp16(uint32_t dst, const void* src) {
    asm volatile("cp.async.cg.shared.global [%0], [%1], 16;"
                 :: "r"(dst), "l"(src) : "memory");
}
#define CP_COMMIT() asm volatile("cp.async.commit_group;" ::: "memory")
#define CP_WAIT0()  asm volatile("cp.async.wait_group 0;" ::: "memory")

#define LDSM4(r, addr)                                                         \
    asm volatile("ldmatrix.sync.aligned.m8n8.x4.shared.b16 {%0,%1,%2,%3}, [%4];" \
                 : "=r"((r)[0]), "=r"((r)[1]), "=r"((r)[2]), "=r"((r)[3])      \
                 : "r"(addr))

__device__ __forceinline__ void mma16816h(float* d, const uint32_t* a,
                                          uint32_t b0, uint32_t b1) {
    asm volatile(
        "mma.sync.aligned.m16n8k16.row.col.f32.f16.f16.f32 "
        "{%0,%1,%2,%3}, {%4,%5,%6,%7}, {%8,%9}, {%0,%1,%2,%3};"
        : "+f"(d[0]), "+f"(d[1]), "+f"(d[2]), "+f"(d[3])
        : "r"(a[0]), "r"(a[1]), "r"(a[2]), "r"(a[3]), "r"(b0), "r"(b1));
}

// packed f32x2 helpers (k_pool)
__device__ __forceinline__ unsigned long long pk2(float lo, float hi) {
    unsigned long long r;
    asm("mov.b64 %0, {%1, %2};" : "=l"(r) : "f"(lo), "f"(hi));
    return r;
}
__device__ __forceinline__ unsigned long long fma2(unsigned long long a,
                                                   unsigned long long b,
                                                   unsigned long long c) {
    unsigned long long d;
    asm("fma.rn.f32x2 %0, %1, %2, %3;" : "=l"(d) : "l"(a), "l"(b), "l"(c));
    return d;
}
__device__ __forceinline__ float2 upk2(unsigned long long v) {
    float lo, hi;
    asm("mov.b64 {%0, %1}, %2;" : "=f"(lo), "=f"(hi) : "l"(v));
    return make_float2(lo, hi);
}

// fast gate: sigmoid(zi)*tanh(zj) via MUFU-based __expf (overflow-safe tanh)
__device__ __forceinline__ float gate_fn(float zi, float zj) {
    float s = __fdividef(1.0f, 1.0f + __expf(-zi));
    float e = __expf(-2.0f * fabsf(zj));
    float th = __fdividef(1.0f - e, 1.0f + e);
    th = copysignf(th, zj);
    return s * th;
}

// SMEM map (dynamic):
//  2 stages of 24576B: A fp16 +0 (8KB, 128 rows x 64B), B fp16 +8192 (16KB)
//  epilogue reuses [0,135168) as fp32 [128][264] (padded); bias at 135168
#define STG     24576
#define SM_EXW  264
#define SM_BIAS 135168
#define SM_TOT  136192

// ============================================================================
// k_wconv: convert+tile weights: g_w[(c*512+n)*32+kk], f = c*32+kk
// ============================================================================
__global__ __launch_bounds__(256) void k_wconv(const float* __restrict__ Wi,
                                               const float* __restrict__ Wj) {
    int i = blockIdx.x * 256 + threadIdx.x;   // 0..163839
    int c  = i >> 14;
    int r  = i & 16383;
    int n  = r >> 5;
    int kk = r & 31;
    int f  = c * 32 + kk;
    float v = (n < 256) ? Wi[n * Ff + f] : Wj[(n - 256) * Ff + f];
    g_w[i] = __float2half_rn(v);
}

// ============================================================================
// k_gemm_mma: dual GEMM (single-pass fp16 HMMA) + fast gate + partial norm.
// CTA: 128M x 256N (128 Di-cols + 128 Dj-cols at offset nt*128).
// 512 thr = 16 warps; warp (wm=wid>>1, wn=wid&1): tile 16m x 128n.
// Double-buffered cp.async (R13-proven structure). xall written as fp16.
// ============================================================================
__global__ __launch_bounds__(512, 1) void k_gemm_mma(
    const float* __restrict__ x,
    const float* __restrict__ bi, const float* __restrict__ bj)
{
    extern __shared__ __align__(128) char smem[];
    const uint32_t sb = smem_u32(smem);
    const int t    = threadIdx.x;
    const int lane = t & 31;
    const int wid  = t >> 5;
    const int wm   = wid >> 1;            // 0..7
    const int wn   = wid & 1;             // 0..1
    const int m0   = blockIdx.x * 128;
    const int nt   = blockIdx.y;          // 0/1: which 128-col slice of Di/Dj

    // bias preload for this CTA's 128 Di + 128 Dj cols
    float* biasS = (float*)(smem + SM_BIAS);
    if (t < 128)            biasS[t] = bi[nt * 128 + t];
    else if (t < 256)       biasS[t] = bj[nt * 128 + (t - 128)];

    float acc[16][4] = {};

    // A addressing: thread owns row t>>2, 8 floats at col (t&3)*8
    const int xrow = t >> 2, xc = t & 3;
    const float* xptr = x + (size_t)(m0 + xrow) * Ff + xc * 8;

    // ---- B issue into stage st for chunk it (256 rows x 64B fp16)
    auto issueB = [&](int it, int st) {
        uint32_t bB = sb + st * STG + 8192;
#pragma unroll
        for (int i = 0; i < 2; i++) {
            int e    = t + i * 512;        // 0..1023
            int brow = e >> 2;             // 0..255
            int kc   = e & 3;
            int gn   = nt * 128 + brow + (brow & 128);  // global n in [0,512)
            uint32_t so = swz((uint32_t)brow * 64 + kc * 16);
            cp16(bB + so, g_w + (size_t)it * 16384 + (size_t)gn * 32 + kc * 8);
        }
    };
    // ---- A convert fp32 -> fp16 (8 vals/thread), STS swizzled
    auto stsA = [&](float4 v0, float4 v1, int st) {
        __half2 h0 = __floats2half2_rn(v0.x, v0.y);
        __half2 h1 = __floats2half2_rn(v0.z, v0.w);
        __half2 h2 = __floats2half2_rn(v1.x, v1.y);
        __half2 h3 = __floats2half2_rn(v1.z, v1.w);
        uint4 pv = make_uint4(*(uint32_t*)&h0, *(uint32_t*)&h1,
                              *(uint32_t*)&h2, *(uint32_t*)&h3);
        uint32_t off = swz((uint32_t)xrow * 64 + xc * 16);
        *(uint4*)(smem + st * STG + off) = pv;
    };
    // ---- compute one k32 chunk from stage st
    auto compute = [&](int st) {
        uint32_t aB = sb + st * STG;
        uint32_t bB = aB + 8192;
        const uint32_t arow = wm * 16 + (lane & 7) + ((lane >> 3) & 1) * 8;
        const uint32_t c16  = (lane >> 4) & 1;
        const uint32_t brow = wn * 128 + (lane & 7) + ((lane >> 3) & 1) * 8;
#pragma unroll
        for (int k16 = 0; k16 < 2; k16++) {
            uint32_t ao = swz(arow * 64 + k16 * 32 + c16 * 16);
            uint32_t a4[4];
            LDSM4(a4, aB + ao);
#pragma unroll
            for (int bn = 0; bn < 8; bn++) {
                uint32_t bo = swz((brow + bn * 16) * 64 + k16 * 32 + c16 * 16);
                uint32_t b4[4];
                LDSM4(b4, bB + bo);
                mma16816h(acc[bn * 2],     a4, b4[0], b4[2]);
                mma16816h(acc[bn * 2 + 1], a4, b4[1], b4[3]);
            }
        }
    };

    // ---- prologue: chunk 0 into buf 0
    stsA(*(const float4*)xptr, *(const float4*)(xptr + 4), 0);
    issueB(0, 0);
    CP_COMMIT();

    // ---- main loop: 10 chunks, double buffered
    for (int it = 0; it < 10; it++) {
        int buf = it & 1;
        CP_WAIT0();
        __syncthreads();
        float4 xn0, xn1;
        if (it < 9) {
            xn0 = *(const float4*)(xptr + (it + 1) * 32);
            xn1 = *(const float4*)(xptr + (it + 1) * 32 + 4);
            issueB(it + 1, buf ^ 1);
            CP_COMMIT();
        }
        compute(buf);
        if (it < 9) stsA(xn0, xn1, buf ^ 1);
    }
    __syncthreads();

    // ---- epilogue: exchange acc via smem fp32 [128][264] (padded stride)
    float* ex = (float*)smem;
#pragma unroll
    for (int fn = 0; fn < 16; fn++) {
        int col = wn * 128 + fn * 8 + (lane & 3) * 2;
        int row = wm * 16 + (lane >> 2);
        ex[row * SM_EXW + col]           = acc[fn][0];
        ex[row * SM_EXW + col + 1]       = acc[fn][1];
        ex[(row + 8) * SM_EXW + col]     = acc[fn][2];
        ex[(row + 8) * SM_EXW + col + 1] = acc[fn][3];
    }
    __syncthreads();

    // gate + write g_xh (fp16) + partial norm. thread: row t>>2, 32 cols
    const int grow = t >> 2, gc = t & 3;
    float nrm = 0.0f;
#pragma unroll
    for (int j = 0; j < 8; j++) {
        int hl = gc * 4 + j * 16;     // local Di col 0..127
        float4 di = *(float4*)&ex[grow * SM_EXW + hl];
        float4 dj = *(float4*)&ex[grow * SM_EXW + 128 + hl];
        float4 bi4 = *(float4*)&biasS[hl];
        float4 bj4 = *(float4*)&biasS[128 + hl];
        float4 o;
        o.x = gate_fn(di.x + bi4.x, dj.x + bj4.x);
        o.y = gate_fn(di.y + bi4.y, dj.y + bj4.y);
        o.z = gate_fn(di.z + bi4.z, dj.z + bj4.z);
        o.w = gate_fn(di.w + bi4.w, dj.w + bj4.w);
        nrm += o.x * o.x + o.y * o.y + o.z * o.z + o.w * o.w;
        __half2 p0 = __floats2half2_rn(o.x, o.y);
        __half2 p1 = __floats2half2_rn(o.z, o.w);
        uint2 pv = make_uint2(*(uint32_t*)&p0, *(uint32_t*)&p1);
        *(uint2*)&g_xh[(size_t)(m0 + grow) * Hh + nt * 128 + hl] = pv;
    }
    nrm += __shfl_xor_sync(0xFFFFFFFFu, nrm, 1);
    nrm += __shfl_xor_sync(0xFFFFFFFFu, nrm, 2);
    if ((lane & 3) == 0) g_np[(size_t)nt * Mtot + m0 + grow] = nrm;
}

// ============================================================================
// k_weight: masked softmax over nodes. One block per (b,s).
// norm = sqrt(p0 + p1) from the two GEMM partials. Fast __expf.
// ============================================================================
__global__ __launch_bounds__(256) void k_weight(const float* __restrict__ node_map,
                                                float* __restrict__ wout) {
    __shared__ float e[Nn];
    __shared__ float red[256];
    int bs = blockIdx.x;
    int b  = bs >> 5;
    const float* nm  = node_map + (size_t)bs * Nn;
    const float* np0 = g_np + (size_t)b * Nn;
    const float* np1 = g_np + (size_t)Mtot + (size_t)b * Nn;
    int t = threadIdx.x;
    float part = 0.0f;
    for (int n = t; n < Nn; n += 256) {
        float v  = nm[n] * sqrtf(np0[n] + np1[n]);
        float ev = (v > 0.0f) ? __expf(v) : 0.0f;
        e[n] = ev;
        part += ev;
    }
    red[t] = part;
    __syncthreads();
#pragma unroll
    for (int o = 128; o > 0; o >>= 1) {
        if (t < o) red[t] += red[t + o];
        __syncthreads();
    }
    float sum = red[0];
    float inv = (sum > 0.0f) ? (1.0f / sum) : 0.0f;
    float* wrow = wout + (size_t)bs * Nn;
    for (int n = t; n < Nn; n += 256) wrow[n] = e[n] * inv;
}

// ============================================================================
// k_pool: split-K pooled partials, full-H blocks, FFMA2.
// g_xh is fp16 -> convert to fp32 at STS time; accumulate fp32.
// ============================================================================
__global__ __launch_bounds__(256) void k_pool(const float* __restrict__ w) {
    __shared__ float xs[32][256];   // 32 KB
    __shared__ float ws[32][32];    //  4 KB
    const int chunk = blockIdx.x;
    const int b     = blockIdx.z;
    const int t     = threadIdx.x;
    const int h1 = (t & 31) * 4;
    const int sq = (t >> 5) * 4;
    const int nbase = chunk * (Nn / NSPLIT);

    unsigned long long acc2[4][4];
    const unsigned long long zz = pk2(0.0f, 0.0f);
#pragma unroll
    for (int i = 0; i < 4; i++)
#pragma unroll
        for (int j = 0; j < 4; j++) acc2[i][j] = zz;

    for (int n0 = 0; n0 < Nn / NSPLIT; n0 += 32) {
        __syncthreads();
#pragma unroll
        for (int i = 0; i < 4; i++) {
            int e  = t + i * 256;          // 0..1023
            int nn = e >> 5;               // 0..31
            int hh = (e & 31) * 8;         // 0..248
            uint4 v = *(const uint4*)&g_xh[(size_t)(b * Nn + nbase + n0 + nn) * Hh + hh];
            float2 f0 = __half22float2(*(__half2*)&v.x);
            float2 f1 = __half22float2(*(__half2*)&v.y);
            float2 f2 = __half22float2(*(__half2*)&v.z);
            float2 f3 = __half22float2(*(__half2*)&v.w);
            *(float4*)&xs[nn][hh]     = make_float4(f0.x, f0.y, f1.x, f1.y);
            *(float4*)&xs[nn][hh + 4] = make_float4(f2.x, f2.y, f3.x, f3.y);
        }
        {
            int s  = t >> 3;
            int nn = (t & 7) * 4;
            float4 wv = *(const float4*)&w[(size_t)(b * Ss + s) * Nn + nbase + n0 + nn];
            ws[nn + 0][s] = wv.x; ws[nn + 1][s] = wv.y;
            ws[nn + 2][s] = wv.z; ws[nn + 3][s] = wv.w;
        }
        __syncthreads();
#pragma unroll
        for (int nc = 0; nc < 32; nc++) {
            ulonglong2 xa = *(const ulonglong2*)&xs[nc][h1];
            ulonglong2 xb = *(const ulonglong2*)&xs[nc][128 + h1];
            float4 wv = *(const float4*)&ws[nc][sq];
            unsigned long long wp[4];
            wp[0] = pk2(wv.x, wv.x); wp[1] = pk2(wv.y, wv.y);
            wp[2] = pk2(wv.z, wv.z); wp[3] = pk2(wv.w, wv.w);
#pragma unroll
            for (int i = 0; i < 4; i++) {
                acc2[i][0] = fma2(wp[i], xa.x, acc2[i][0]);
                acc2[i][1] = fma2(wp[i], xa.y, acc2[i][1]);
                acc2[i][2] = fma2(wp[i], xb.x, acc2[i][2]);
                acc2[i][3] = fma2(wp[i], xb.y, acc2[i][3]);
            }
        }
    }
#pragma unroll
    for (int i = 0; i < 4; i++) {
        float2 a0 = upk2(acc2[i][0]), a1 = upk2(acc2[i][1]);
        float2 b0 = upk2(acc2[i][2]), b1 = upk2(acc2[i][3]);
        size_t base = (size_t)((chunk * Bq + b) * Ss + sq + i) * Hh;
        *(float4*)&g_part[base + h1]       = make_float4(a0.x, a0.y, a1.x, a1.y);
        *(float4*)&g_part[base + 128 + h1] = make_float4(b0.x, b0.y, b1.x, b1.y);
    }
}

// ============================================================================
// k_final: deterministic split-K reduce + tanh (precise tanhf on output)
// ============================================================================
__global__ __launch_bounds__(256) void k_final(float* __restrict__ out) {
    int g = blockIdx.x * blockDim.x + threadIdx.x;
    float s = 0.0f;
#pragma unroll
    for (int c = 0; c < NSPLIT; c++) s += g_part[(size_t)c * (Bq * Ss * Hh) + g];
    out[g] = tanhf(s);
}

// ============================================================================
extern "C" void kernel_launch(void* const* d_in, const int* in_sizes, int n_in,
                              void* d_out, int out_size) {
    const float* x        = (const float*)d_in[0];
    const float* node_map = (const float*)d_in[1];
    const float* Wi       = (const float*)d_in[2];
    const float* bi       = (const float*)d_in[3];
    const float* Wj       = (const float*)d_in[4];
    const float* bj       = (const float*)d_in[5];
    float* out  = (float*)d_out;
    float* wout = out + (size_t)Bq * Ss * Hh;

    cudaFuncSetAttribute(k_gemm_mma, cudaFuncAttributeMaxDynamicSharedMemorySize, SM_TOT);

    k_wconv<<<(512 * Ff) / 256, 256>>>(Wi, Wj);
    k_gemm_mma<<<dim3(Mtot / 128, 2), 512, SM_TOT>>>(x, bi, bj);
    k_weight<<<Bq * Ss, 256>>>(node_map, wout);
    k_pool<<<dim3(NSPLIT, 1, Bq), 256>>>(wout);
    k_final<<<(Bq * Ss * Hh) / 256, 256>>>(out);
}

// round 16
// speedup vs baseline: 1.3702x; 1.2824x over previous
#include <cuda_runtime.h>
#include <cuda_fp16.h>
#include <math.h>
#include <stdint.h>

// Problem constants
#define Bq   8
#define Nn   8192
#define Hh   256
#define Ff   320
#define Ss   32
#define Mtot (Bq * Nn)      // 65536
#define NSPLIT 32

// Scratch (static device globals — no cudaMalloc allowed)
__device__ __half g_xh[(size_t)Mtot * Hh];         // gated features fp16 [B*N, H]
__device__ float g_np[2 * Mtot];                   // partial norm^2 (nt 0/1)
__device__ float g_part[(size_t)NSPLIT * Bq * Ss * Hh];  // split-K partials
__device__ __half g_wq[(size_t)Bq * Ss * Nn];      // fp16 softmax weights (pool operand)
// combined weights [Wi;Wj] = 512 rows x 320 cols, fp16,
// tiled as [kchunk 10][n 512][k 32] for direct cp.async
__device__ __half g_w[512 * Ff];

// ======================= helpers ============================================
__device__ __forceinline__ uint32_t smem_u32(const void* p) {
    uint32_t a;
    asm("{ .reg .u64 t; cvta.to.shared.u64 t, %1; cvt.u32.u64 %0, t; }"
        : "=r"(a) : "l"(p));
    return a;
}
// SW64 swizzle for 64B rows: bits[5:4] ^= bits[8:7]
__device__ __forceinline__ uint32_t swz(uint32_t o) {
    return o ^ ((o >> 3) & 0x30);
}
// swizzle for 512B rows: 16B-chunk index ^= row&7
__device__ __forceinline__ uint32_t swzx(uint32_t o) {
    return o ^ (((o >> 9) & 7) << 4);
}
__device__ __forceinline__ void cp16(uint32_t dst, const void* src) {
    asm volatile("cp.async.cg.shared.global [%0], [%1], 16;"
                 :: "r"(dst), "l"(src) : "memory");
}
#define CP_COMMIT() asm volatile("cp.async.commit_group;" ::: "memory")
#define CP_WAIT(n)  asm volatile("cp.async.wait_group %0;" :: "n"(n) : "memory")

#define LDSM4(r, addr)                                                         \
    asm volatile("ldmatrix.sync.aligned.m8n8.x4.shared.b16 {%0,%1,%2,%3}, [%4];" \
                 : "=r"((r)[0]), "=r"((r)[1]), "=r"((r)[2]), "=r"((r)[3])      \
                 : "r"(addr))
#define LDSM4T(r, addr)                                                        \
    asm volatile("ldmatrix.sync.aligned.m8n8.x4.trans.shared.b16 {%0,%1,%2,%3}, [%4];" \
                 : "=r"((r)[0]), "=r"((r)[1]), "=r"((r)[2]), "=r"((r)[3])      \
                 : "r"(addr))

__device__ __forceinline__ void mma16816h(float* d, const uint32_t* a,
                                          uint32_t b0, uint32_t b1) {
    asm volatile(
        "mma.sync.aligned.m16n8k16.row.col.f32.f16.f16.f32 "
        "{%0,%1,%2,%3}, {%4,%5,%6,%7}, {%8,%9}, {%0,%1,%2,%3};"
        : "+f"(d[0]), "+f"(d[1]), "+f"(d[2]), "+f"(d[3])
        : "r"(a[0]), "r"(a[1]), "r"(a[2]), "r"(a[3]), "r"(b0), "r"(b1));
}

// fast gate via MUFU.TANH: sigmoid(zi)*tanh(zj), sigmoid(z)=0.5*(1+tanh(z/2))
__device__ __forceinline__ float gate_fn(float zi, float zj) {
    float si, tj;
    asm("tanh.approx.f32 %0, %1;" : "=f"(si) : "f"(0.5f * zi));
    asm("tanh.approx.f32 %0, %1;" : "=f"(tj) : "f"(zj));
    return (0.5f + 0.5f * si) * tj;
}

// GEMM SMEM map (dynamic):
//  2 stages of 24576B: A fp16 +0 (8KB, 128 rows x 64B), B fp16 +8192 (16KB)
//  nbuf (256 f32) at 49152; bias (256 f32) at 50176
#define STG     24576
#define SM_NB   49152
#define SM_BIAS 50176
#define SM_TOT  51200

// ============================================================================
// k_wconv: convert+tile weights: g_w[(c*512+n)*32+kk], f = c*32+kk
// ============================================================================
__global__ __launch_bounds__(256) void k_wconv(const float* __restrict__ Wi,
                                               const float* __restrict__ Wj) {
    int i = blockIdx.x * 256 + threadIdx.x;   // 0..163839
    int c  = i >> 14;
    int r  = i & 16383;
    int n  = r >> 5;
    int kk = r & 31;
    int f  = c * 32 + kk;
    float v = (n < 256) ? Wi[n * Ff + f] : Wj[(n - 256) * Ff + f];
    g_w[i] = __float2half_rn(v);
}

// ============================================================================
// k_gemm_mma: dual GEMM (fp16 HMMA) + in-register gate + partial norm.
// CTA: 128M x 256N. B rows interleaved: local row r: q=r>>4, rr=r&15;
// global n = (q&1)*256 + nt*128 + (q>>1)*16 + rr  (q even = Di, odd = Dj,
// both halves of an h-block live in the SAME warp's adjacent bn frags).
// 512 thr = 16 warps; warp (wm=wid>>1, wn=wid&1): tile 16m x 128n.
// ============================================================================
__global__ __launch_bounds__(512, 1) void k_gemm_mma(
    const float* __restrict__ x,
    const float* __restrict__ bi, const float* __restrict__ bj)
{
    extern __shared__ __align__(128) char smem[];
    const uint32_t sb = smem_u32(smem);
    const int t    = threadIdx.x;
    const int lane = t & 31;
    const int wid  = t >> 5;
    const int wm   = wid >> 1;            // 0..7
    const int wn   = wid & 1;             // 0..1
    const int m0   = blockIdx.x * 128;
    const int nt   = blockIdx.y;          // 0/1: which 128-col slice of Di/Dj

    // bias preload: biasS[0..127]=bi slice, [128..255]=bj slice
    float* biasS = (float*)(smem + SM_BIAS);
    if (t < 128)            biasS[t] = bi[nt * 128 + t];
    else if (t < 256)       biasS[t] = bj[nt * 128 + (t - 128)];

    float acc[16][4] = {};

    // A addressing: thread owns row t>>2, 8 floats at col (t&3)*8
    const int xrow = t >> 2, xc = t & 3;
    const float* xptr = x + (size_t)(m0 + xrow) * Ff + xc * 8;

    // ---- B issue into stage st for chunk it (256 rows x 64B fp16, interleaved)
    auto issueB = [&](int it, int st) {
        uint32_t bB = sb + st * STG + 8192;
#pragma unroll
        for (int i = 0; i < 2; i++) {
            int e    = t + i * 512;        // 0..1023
            int brow = e >> 2;             // local row 0..255
            int kc   = e & 3;
            int q    = brow >> 4;
            int rr   = brow & 15;
            int gn   = (q & 1) * 256 + nt * 128 + (q >> 1) * 16 + rr;
            uint32_t so = swz((uint32_t)brow * 64 + kc * 16);
            cp16(bB + so, g_w + (size_t)it * 16384 + (size_t)gn * 32 + kc * 8);
        }
    };
    // ---- A convert fp32 -> fp16 (8 vals/thread), STS swizzled
    auto stsA = [&](float4 v0, float4 v1, int st) {
        __half2 h0 = __floats2half2_rn(v0.x, v0.y);
        __half2 h1 = __floats2half2_rn(v0.z, v0.w);
        __half2 h2 = __floats2half2_rn(v1.x, v1.y);
        __half2 h3 = __floats2half2_rn(v1.z, v1.w);
        uint4 pv = make_uint4(*(uint32_t*)&h0, *(uint32_t*)&h1,
                              *(uint32_t*)&h2, *(uint32_t*)&h3);
        uint32_t off = swz((uint32_t)xrow * 64 + xc * 16);
        *(uint4*)(smem + st * STG + off) = pv;
    };
    // ---- compute one k32 chunk from stage st
    auto compute = [&](int st) {
        uint32_t aB = sb + st * STG;
        uint32_t bB = aB + 8192;
        const uint32_t arow = wm * 16 + (lane & 7) + ((lane >> 3) & 1) * 8;
        const uint32_t c16  = (lane >> 4) & 1;
        const uint32_t brow = wn * 128 + (lane & 7) + ((lane >> 3) & 1) * 8;
#pragma unroll
        for (int k16 = 0; k16 < 2; k16++) {
            uint32_t ao = swz(arow * 64 + k16 * 32 + c16 * 16);
            uint32_t a4[4];
            LDSM4(a4, aB + ao);
#pragma unroll
            for (int bn = 0; bn < 8; bn++) {
                uint32_t bo = swz((brow + bn * 16) * 64 + k16 * 32 + c16 * 16);
                uint32_t b4[4];
                LDSM4(b4, bB + bo);
                mma16816h(acc[bn * 2],     a4, b4[0], b4[2]);
                mma16816h(acc[bn * 2 + 1], a4, b4[1], b4[3]);
            }
        }
    };

    // ---- prologue: chunk 0 into buf 0
    stsA(*(const float4*)xptr, *(const float4*)(xptr + 4), 0);
    issueB(0, 0);
    CP_COMMIT();

    // ---- main loop: 10 chunks, double buffered
    for (int it = 0; it < 10; it++) {
        int buf = it & 1;
        CP_WAIT(0);
        __syncthreads();
        float4 xn0, xn1;
        if (it < 9) {
            xn0 = *(const float4*)(xptr + (it + 1) * 32);
            xn1 = *(const float4*)(xptr + (it + 1) * 32 + 4);
            issueB(it + 1, buf ^ 1);
            CP_COMMIT();
        }
        compute(buf);
        if (it < 9) stsA(xn0, xn1, buf ^ 1);
    }

    // ---- in-register epilogue: gate + STG fp16 + norm
    // bn=2e (Di) / bn=2e+1 (Dj) share h-block hbl = wn*4+e.
    const int r0 = m0 + wm * 16 + (lane >> 2);
    const int c2 = (lane & 3) * 2;
    float nrm0 = 0.0f, nrm1 = 0.0f;
#pragma unroll
    for (int e = 0; e < 4; e++) {
        int hbl = wn * 4 + e;
#pragma unroll
        for (int hf = 0; hf < 2; hf++) {
            int hl = hbl * 16 + hf * 8 + c2;        // local col 0..127
            float2 bi2 = *(float2*)&biasS[hl];
            float2 bj2 = *(float2*)&biasS[128 + hl];
            float* aD = acc[4 * e + hf];
            float* aJ = acc[4 * e + 2 + hf];
            float o00 = gate_fn(aD[0] + bi2.x, aJ[0] + bj2.x);
            float o01 = gate_fn(aD[1] + bi2.y, aJ[1] + bj2.y);
            float o10 = gate_fn(aD[2] + bi2.x, aJ[2] + bj2.x);
            float o11 = gate_fn(aD[3] + bi2.y, aJ[3] + bj2.y);
            nrm0 += o00 * o00 + o01 * o01;
            nrm1 += o10 * o10 + o11 * o11;
            __half2 p0 = __floats2half2_rn(o00, o01);
            __half2 p1 = __floats2half2_rn(o10, o11);
            int hg = nt * 128 + hl;
            *(uint32_t*)&g_xh[(size_t)r0 * Hh + hg]       = *(uint32_t*)&p0;
            *(uint32_t*)&g_xh[(size_t)(r0 + 8) * Hh + hg] = *(uint32_t*)&p1;
        }
    }
    nrm0 += __shfl_xor_sync(0xFFFFFFFFu, nrm0, 1);
    nrm0 += __shfl_xor_sync(0xFFFFFFFFu, nrm0, 2);
    nrm1 += __shfl_xor_sync(0xFFFFFFFFu, nrm1, 1);
    nrm1 += __shfl_xor_sync(0xFFFFFFFFu, nrm1, 2);
    float* nbuf = (float*)(smem + SM_NB);
    if ((lane & 3) == 0) {
        nbuf[wn * 128 + wm * 16 + (lane >> 2)]     = nrm0;
        nbuf[wn * 128 + wm * 16 + (lane >> 2) + 8] = nrm1;
    }
    __syncthreads();
    if (t < 128)
        g_np[(size_t)nt * Mtot + m0 + t] = nbuf[t] + nbuf[128 + t];
}

// ============================================================================
// k_weight: masked softmax over nodes. One block per (b,s).
// Writes fp32 weight output AND fp16 copy for the HMMA pool.
// ============================================================================
__global__ __launch_bounds__(256) void k_weight(const float* __restrict__ node_map,
                                                float* __restrict__ wout) {
    __shared__ float e[Nn];
    __shared__ float red[256];
    int bs = blockIdx.x;
    int b  = bs >> 5;
    const float* nm  = node_map + (size_t)bs * Nn;
    const float* np0 = g_np + (size_t)b * Nn;
    const float* np1 = g_np + (size_t)Mtot + (size_t)b * Nn;
    int t = threadIdx.x;
    float part = 0.0f;
    for (int n = t; n < Nn; n += 256) {
        float v  = nm[n] * sqrtf(np0[n] + np1[n]);
        float ev = (v > 0.0f) ? __expf(v) : 0.0f;
        e[n] = ev;
        part += ev;
    }
    red[t] = part;
    __syncthreads();
#pragma unroll
    for (int o = 128; o > 0; o >>= 1) {
        if (t < o) red[t] += red[t + o];
        __syncthreads();
    }
    float sum = red[0];
    float inv = (sum > 0.0f) ? (1.0f / sum) : 0.0f;
    float* wrow = wout + (size_t)bs * Nn;
    __half* wqrow = g_wq + (size_t)bs * Nn;
    for (int n = t; n < Nn; n += 256) {
        float wv = e[n] * inv;
        wrow[n]  = wv;
        wqrow[n] = __float2half_rn(wv);
    }
}

// ============================================================================
// k_pool: HMMA pooled GEMM, split-K. D[s,h] = sum_n w[s,n] * xh[n,h].
// grid (32 chunks, 1, 8 b), 256 thr = 8 warps (wm=wid>>2 m16, wn=wid&3 n64).
// w tile [32 s][256 k] fp16 resident; xh streamed in 32-node tiles (3 bufs).
// xh rows are [node][h] -> ldmatrix.trans for the B operand.
// ============================================================================
__global__ __launch_bounds__(256, 1) void k_pool() {
    extern __shared__ __align__(128) char psm[];
    const uint32_t sb = smem_u32(psm);
    const int t    = threadIdx.x;
    const int lane = t & 31;
    const int wid  = t >> 5;
    const int wm   = wid >> 2;            // 0..1
    const int wn   = wid & 3;             // 0..3
    const int chunk = blockIdx.x;         // 0..31
    const int b     = blockIdx.z;         // 0..7
    const int nbase = chunk * 256;

    // ---- load w tile: 32 rows x 512B (fp16, swzx)
#pragma unroll
    for (int i = 0; i < 4; i++) {
        int e  = t + i * 256;             // 0..1023
        int s  = e >> 5;
        int kc = e & 31;
        cp16(sb + swzx((uint32_t)s * 512 + kc * 16),
             g_wq + (size_t)(b * Ss + s) * Nn + nbase + kc * 8);
    }
    // ---- xh tile streamer (32 nodes x 512B)
    auto issueX = [&](int kk, int st) {
        uint32_t xb = sb + 16384 + st * 16384;
#pragma unroll
        for (int i = 0; i < 4; i++) {
            int e  = t + i * 256;
            int nn = e >> 5;
            int kc = e & 31;
            cp16(xb + swzx((uint32_t)nn * 512 + kc * 16),
                 g_xh + (size_t)(b * Nn + nbase + kk * 32 + nn) * Hh + kc * 8);
        }
    };
    issueX(0, 0); CP_COMMIT();            // group: w + x0
    issueX(1, 1); CP_COMMIT();

    float acc[8][4] = {};

    for (int kk = 0; kk < 8; kk++) {
        if (kk < 7) CP_WAIT(1); else CP_WAIT(0);
        __syncthreads();
        if (kk < 6) { issueX(kk + 2, (kk + 2) % 3); CP_COMMIT(); }
        uint32_t xb = sb + 16384 + (kk % 3) * 16384;
#pragma unroll
        for (int k16 = 0; k16 < 2; k16++) {
            const int kr0 = k16 * 16;
            // A frag: w[s][k] row-major, m16k16 at (wm*16, kk*32+kr0)
            uint32_t a4[4];
            {
                uint32_t r  = wm * 16 + (lane & 15);
                uint32_t cb = (uint32_t)(kk * 32 + kr0) * 2 + ((lane >> 4) & 1) * 16;
                LDSM4(a4, sb + swzx(r * 512 + cb));
            }
            // B frags: xh[node][h], trans -> (b0,b1) n8 blk0, (b2,b3) n8 blk1
#pragma unroll
            for (int j = 0; j < 4; j++) {
                uint32_t r  = kr0 + (lane & 7) + ((lane >> 3) & 1) * 8;
                uint32_t cb = (uint32_t)(wn * 64 + j * 16) * 2 + ((lane >> 4) & 1) * 16;
                uint32_t b4[4];
                LDSM4T(b4, xb + swzx(r * 512 + cb));
                mma16816h(acc[2 * j],     a4, b4[0], b4[1]);
                mma16816h(acc[2 * j + 1], a4, b4[2], b4[3]);
            }
        }
    }

    // ---- write fp32 partials
    const int s0 = wm * 16 + (lane >> 2);
    const size_t base = (size_t)(chunk * Bq + b) * Ss * Hh;
#pragma unroll
    for (int j = 0; j < 4; j++) {
#pragma unroll
        for (int hf = 0; hf < 2; hf++) {
            int h = wn * 64 + j * 16 + hf * 8 + (lane & 3) * 2;
            float* a = acc[2 * j + hf];
            *(float2*)&g_part[base + (size_t)s0 * Hh + h]       = make_float2(a[0], a[1]);
            *(float2*)&g_part[base + (size_t)(s0 + 8) * Hh + h] = make_float2(a[2], a[3]);
        }
    }
}

// ============================================================================
// k_final: deterministic split-K reduce + tanh (precise tanhf on output)
// ============================================================================
__global__ __launch_bounds__(256) void k_final(float* __restrict__ out) {
    int g = blockIdx.x * blockDim.x + threadIdx.x;
    float s = 0.0f;
#pragma unroll
    for (int c = 0; c < NSPLIT; c++) s += g_part[(size_t)c * (Bq * Ss * Hh) + g];
    out[g] = tanhf(s);
}

// ============================================================================
extern "C" void kernel_launch(void* const* d_in, const int* in_sizes, int n_in,
                              void* d_out, int out_size) {
    const float* x        = (const float*)d_in[0];
    const float* node_map = (const float*)d_in[1];
    const float* Wi       = (const float*)d_in[2];
    const float* bi       = (const float*)d_in[3];
    const float* Wj       = (const float*)d_in[4];
    const float* bj       = (const float*)d_in[5];
    float* out  = (float*)d_out;
    float* wout = out + (size_t)Bq * Ss * Hh;

    cudaFuncSetAttribute(k_gemm_mma, cudaFuncAttributeMaxDynamicSharedMemorySize, SM_TOT);
    cudaFuncSetAttribute(k_pool, cudaFuncAttributeMaxDynamicSharedMemorySize, 65536);

    k_wconv<<<(512 * Ff) / 256, 256>>>(Wi, Wj);
    k_gemm_mma<<<dim3(Mtot / 128, 2), 512, SM_TOT>>>(x, bi, bj);
    k_weight<<<Bq * Ss, 256>>>(node_map, wout);
    k_pool<<<dim3(NSPLIT, 1, Bq), 256, 65536>>>();
    k_final<<<(Bq * Ss * Hh) / 256, 256>>>(out);
}